// round 15
// baseline (speedup 1.0000x reference)
#include <cuda_runtime.h>
#include <cuda_bf16.h>
#include <cuda_fp16.h>
#include <cstdint>
#include <math_constants.h>

#define NN 50000
#define NE 1600000
#define BB 16384

// ---------------- device scratch ----------------
// g_deg must be zero at entry of every kernel_launch call; k_scan3 restores it.
__device__ __align__(16) float g_x[3][NN * 32];
__device__ __align__(16) __half g_h[3][NN * 128];
__device__ __align__(16) float g_el[3][NN * 4];
__device__ __align__(16) float g_er[3][NN * 4];
__device__ __align__(16) __half g_comb[NN * 384];   // fp16 (numerically free)
__device__ int g_deg[NN];
__device__ int g_rowptr[NN + 1];
__device__ int g_cursor[NN];
__device__ int g_csrc[NE];
__device__ int g_bsum[64];
__device__ int g_bsum2[64];

// ---------------- tensor-core helpers ----------------
__device__ __forceinline__ void ldsm4(uint32_t& r0, uint32_t& r1, uint32_t& r2,
                                      uint32_t& r3, uint32_t addr) {
    asm volatile("ldmatrix.sync.aligned.m8n8.x4.shared.b16 {%0,%1,%2,%3},[%4];"
                 : "=r"(r0), "=r"(r1), "=r"(r2), "=r"(r3)
                 : "r"(addr));
}
__device__ __forceinline__ void mma16816(float* c, uint32_t a0, uint32_t a1,
                                         uint32_t a2, uint32_t a3, uint32_t b0,
                                         uint32_t b1) {
    asm volatile(
        "mma.sync.aligned.m16n8k16.row.col.f32.f16.f16.f32 "
        "{%0,%1,%2,%3},{%4,%5,%6,%7},{%8,%9},{%0,%1,%2,%3};"
        : "+f"(c[0]), "+f"(c[1]), "+f"(c[2]), "+f"(c[3])
        : "r"(a0), "r"(a1), "r"(a2), "r"(a3), "r"(b0), "r"(b1));
}

// ---------------- K0: embedding gathers + degree histogram ------------------
__global__ void k_front(const int* __restrict__ uid, const int* __restrict__ iid,
                        const float* __restrict__ ut, const float* __restrict__ it,
                        float* __restrict__ out, const int* __restrict__ dst) {
    int bx = blockIdx.x;
    if (bx < 4096) {
        int t = bx * 256 + threadIdx.x;
        int c = t & 31;
        int r = (t >> 5) & (BB - 1);
        int which = t >> 19;
        const float4* src = which ? (const float4*)it : (const float4*)ut;
        int id = which ? iid[r] : uid[r];
        float4* dstp = (float4*)out + (which ? BB * 32 : 0);
        dstp[r * 32 + c] = src[id * 32 + c];
    } else {
        int e = (bx - 4096) * 256 + threadIdx.x;
        if (e < NE) atomicAdd(&g_deg[dst[e]], 1);
    }
}

// ---------------- scan stage 1 ----------------------------------------------
__global__ void k_scan1() {
    __shared__ int ws[32];
    int t = threadIdx.x;
    int lane = t & 31;
    int w = t >> 5;
    int i = blockIdx.x * 1024 + t;
    int v = (i < NN) ? g_deg[i] : 0;
    int x = v;
#pragma unroll
    for (int d = 1; d < 32; d <<= 1) {
        int y = __shfl_up_sync(0xffffffffu, x, d);
        if (lane >= d) x += y;
    }
    if (lane == 31) ws[w] = x;
    __syncthreads();
    if (w == 0) {
        int s = ws[lane];
#pragma unroll
        for (int d = 1; d < 32; d <<= 1) {
            int y = __shfl_up_sync(0xffffffffu, s, d);
            if (lane >= d) s += y;
        }
        ws[lane] = s;
    }
    __syncthreads();
    int incl = x + (w ? ws[w - 1] : 0);
    if (i < NN) g_rowptr[i + 1] = incl;
    if (t == 1023) g_bsum[blockIdx.x] = incl;
}

// ---------------- scan stage 2 ----------------------------------------------
__global__ void k_scan2() {
    if (threadIdx.x == 0) {
        int run = 0;
#pragma unroll 1
        for (int b = 0; b < 49; ++b) {
            g_bsum2[b] = run;
            run += g_bsum[b];
        }
    }
}

// ---------------- scan stage 3 ----------------------------------------------
__global__ void k_scan3() {
    int i = blockIdx.x * 1024 + threadIdx.x;
    if (i < NN) {
        int off = g_bsum2[blockIdx.x];
        int incl = g_rowptr[i + 1] + off;
        g_rowptr[i + 1] = incl;
        g_cursor[i] = incl - g_deg[i];
        g_deg[i] = 0;
    }
    if (i == 0) g_rowptr[0] = 0;
}

// ---------------- CSR scatter ------------------------------------------------
__global__ void k_scatter(const int* __restrict__ src, const int* __restrict__ dst) {
    int e = blockIdx.x * 256 + threadIdx.x;
    if (e < NE) {
        int d = dst[e];
        int pos = atomicAdd(&g_cursor[d], 1);
        g_csrc[pos] = src[e];
    }
}

// ---------------- fused modality linears via HMMA, 2-stage pipeline ---------
__global__ void __launch_bounds__(256) k_lin32(
    const float* __restrict__ f0, const float* __restrict__ f1,
    const float* __restrict__ f2, const float* __restrict__ W0,
    const float* __restrict__ W1, const float* __restrict__ W2,
    const float* __restrict__ b0, const float* __restrict__ b1,
    const float* __restrict__ b2) {
    __shared__ __half As[2][128 * 64];
    __shared__ __half Bs[2][32 * 64];
    int m = blockIdx.y;
    const float* A = (m == 0) ? f0 : ((m == 1) ? f1 : f2);
    const float* W = (m == 0) ? W0 : ((m == 1) ? W1 : W2);
    const float* bias = (m == 0) ? b0 : ((m == 1) ? b1 : b2);
    const int K = (m == 0) ? 1024 : ((m == 1) ? 768 : 128);
    float* X = g_x[m];

    int t = threadIdx.x;
    int lane = t & 31;
    int w = t >> 5;
    int br = blockIdx.x * 128;
    uint32_t asb = (uint32_t)__cvta_generic_to_shared(&As[0][0]);
    uint32_t bsb = (uint32_t)__cvta_generic_to_shared(&Bs[0][0]);

    float acc[16];
#pragma unroll
    for (int i = 0; i < 16; ++i) acc[i] = 0.f;

    int aRow = w * 16 + (lane & 15);
    int aColB = (lane >> 4) * 16;
    int aSw = (aRow & 7) * 16;
    int bRow = (lane & 7) + ((lane >> 4) & 1) * 8;
    int bColB = ((lane >> 3) & 1) * 16;
    int bSw = (bRow & 7) * 16;

    int sr = t >> 4;
    int sc4 = (t & 15) * 4;

    float4 va[8];
    float4 vb[2];

#pragma unroll
    for (int i = 0; i < 8; ++i) {
        int r = i * 16 + sr;
        int row = br + r;
        if (row >= NN) row = NN - 1;
        va[i] = *reinterpret_cast<const float4*>(&A[(long)row * K + sc4]);
    }
#pragma unroll
    for (int i = 0; i < 2; ++i) {
        int r = i * 16 + sr;
        vb[i] = *reinterpret_cast<const float4*>(&W[r * K + sc4]);
    }
#pragma unroll
    for (int i = 0; i < 8; ++i) {
        int r = i * 16 + sr;
        int off = r * 128 + ((sc4 * 2) ^ ((r & 7) * 16));
        __half2* p = reinterpret_cast<__half2*>(reinterpret_cast<char*>(&As[0][0]) + off);
        p[0] = __floats2half2_rn(va[i].x, va[i].y);
        p[1] = __floats2half2_rn(va[i].z, va[i].w);
    }
#pragma unroll
    for (int i = 0; i < 2; ++i) {
        int r = i * 16 + sr;
        int off = r * 128 + ((sc4 * 2) ^ ((r & 7) * 16));
        __half2* p = reinterpret_cast<__half2*>(reinterpret_cast<char*>(&Bs[0][0]) + off);
        p[0] = __floats2half2_rn(vb[i].x, vb[i].y);
        p[1] = __floats2half2_rn(vb[i].z, vb[i].w);
    }
    __syncthreads();

    int nIter = K >> 6;
    for (int it = 0; it < nIter; ++it) {
        int cur = it & 1;
        if (it + 1 < nIter) {
            int k0 = (it + 1) * 64;
#pragma unroll
            for (int i = 0; i < 8; ++i) {
                int r = i * 16 + sr;
                int row = br + r;
                if (row >= NN) row = NN - 1;
                va[i] = *reinterpret_cast<const float4*>(&A[(long)row * K + k0 + sc4]);
            }
#pragma unroll
            for (int i = 0; i < 2; ++i) {
                int r = i * 16 + sr;
                vb[i] = *reinterpret_cast<const float4*>(&W[r * K + k0 + sc4]);
            }
        }
        uint32_t aBase = asb + cur * 16384 + aRow * 128;
        uint32_t bBase0 = bsb + cur * 4096 + bRow * 128;
        uint32_t bBase1 = bBase0 + 16 * 128;
#pragma unroll
        for (int ks = 0; ks < 4; ++ks) {
            uint32_t a0, a1, a2, a3;
            ldsm4(a0, a1, a2, a3, aBase + ((ks * 32 + aColB) ^ aSw));
            uint32_t c0, c1, c2, c3;
            uint32_t d0, d1, d2, d3;
            int bcb = ks * 32 + bColB;
            ldsm4(c0, c1, c2, c3, bBase0 + (bcb ^ bSw));
            ldsm4(d0, d1, d2, d3, bBase1 + (bcb ^ bSw));
            mma16816(acc + 0, a0, a1, a2, a3, c0, c1);
            mma16816(acc + 4, a0, a1, a2, a3, c2, c3);
            mma16816(acc + 8, a0, a1, a2, a3, d0, d1);
            mma16816(acc + 12, a0, a1, a2, a3, d2, d3);
        }
        if (it + 1 < nIter) {
            int nxt = 1 - cur;
#pragma unroll
            for (int i = 0; i < 8; ++i) {
                int r = i * 16 + sr;
                int off = r * 128 + ((sc4 * 2) ^ ((r & 7) * 16));
                __half2* p = reinterpret_cast<__half2*>(
                    reinterpret_cast<char*>(&As[nxt][0]) + off);
                p[0] = __floats2half2_rn(va[i].x, va[i].y);
                p[1] = __floats2half2_rn(va[i].z, va[i].w);
            }
#pragma unroll
            for (int i = 0; i < 2; ++i) {
                int r = i * 16 + sr;
                int off = r * 128 + ((sc4 * 2) ^ ((r & 7) * 16));
                __half2* p = reinterpret_cast<__half2*>(
                    reinterpret_cast<char*>(&Bs[nxt][0]) + off);
                p[0] = __floats2half2_rn(vb[i].x, vb[i].y);
                p[1] = __floats2half2_rn(vb[i].z, vb[i].w);
            }
        }
        __syncthreads();
    }

    int r0 = br + w * 16 + (lane >> 2);
    int col0 = (lane & 3) * 2;
#pragma unroll
    for (int g = 0; g < 4; ++g) {
        int col = g * 8 + col0;
        float bv0 = bias[col];
        float bv1 = bias[col + 1];
        if (r0 < NN) {
            float2 o;
            o.x = fmaxf(acc[g * 4 + 0] + bv0, 0.f);
            o.y = fmaxf(acc[g * 4 + 1] + bv1, 0.f);
            *reinterpret_cast<float2*>(&X[r0 * 32 + col]) = o;
        }
        if (r0 + 8 < NN) {
            float2 o;
            o.x = fmaxf(acc[g * 4 + 2] + bv0, 0.f);
            o.y = fmaxf(acc[g * 4 + 3] + bv1, 0.f);
            *reinterpret_cast<float2*>(&X[(r0 + 8) * 32 + col]) = o;
        }
    }
}

// ---------------- GAT fc via HMMA + fused attention logits ------------------
__global__ void __launch_bounds__(256) k_gatfc(
    const float* __restrict__ gW0, const float* __restrict__ gW1,
    const float* __restrict__ gW2, const float* __restrict__ al0,
    const float* __restrict__ al1, const float* __restrict__ al2,
    const float* __restrict__ ar0, const float* __restrict__ ar1,
    const float* __restrict__ ar2) {
    __shared__ __half As[64 * 64];
    __shared__ __half Bs[128 * 64];
    __shared__ float als[128];
    __shared__ float ars[128];
    int m = blockIdx.y;
    const float* gW = (m == 0) ? gW0 : ((m == 1) ? gW1 : gW2);
    const float* al = (m == 0) ? al0 : ((m == 1) ? al1 : al2);
    const float* ar = (m == 0) ? ar0 : ((m == 1) ? ar1 : ar2);
    const float* X = g_x[m];
    __half* Hout = g_h[m];
    float* ELout = g_el[m];
    float* ERout = g_er[m];

    int t = threadIdx.x;
    int lane = t & 31;
    int w = t >> 5;
    int br = blockIdx.x * 64;
    uint32_t asb = (uint32_t)__cvta_generic_to_shared(&As[0]);
    uint32_t bsb = (uint32_t)__cvta_generic_to_shared(&Bs[0]);

    if (t < 128) als[t] = al[t];
    else ars[t - 128] = ar[t - 128];

#pragma unroll
    for (int i = 0; i < 2; ++i) {
        int idx = i * 256 + t;
        int r = idx >> 3;
        int c4 = (idx & 7) * 4;
        int row = br + r;
        if (row >= NN) row = NN - 1;
        float4 v = *reinterpret_cast<const float4*>(&X[(long)row * 32 + c4]);
        int off = r * 128 + ((c4 * 2) ^ ((r & 7) * 16));
        __half2* p = reinterpret_cast<__half2*>(reinterpret_cast<char*>(&As[0]) + off);
        p[0] = __floats2half2_rn(v.x, v.y);
        p[1] = __floats2half2_rn(v.z, v.w);
    }
#pragma unroll
    for (int i = 0; i < 4; ++i) {
        int idx = i * 256 + t;
        int r = idx >> 3;
        int c4 = (idx & 7) * 4;
        float4 v = *reinterpret_cast<const float4*>(&gW[r * 32 + c4]);
        int off = r * 128 + ((c4 * 2) ^ ((r & 7) * 16));
        __half2* p = reinterpret_cast<__half2*>(reinterpret_cast<char*>(&Bs[0]) + off);
        p[0] = __floats2half2_rn(v.x, v.y);
        p[1] = __floats2half2_rn(v.z, v.w);
    }
    __syncthreads();

    float acc[32];
#pragma unroll
    for (int i = 0; i < 32; ++i) acc[i] = 0.f;

    int rg = w >> 1;
    int colGrp = (w & 1) * 64;
    int aRow = rg * 16 + (lane & 15);
    int aColB = (lane >> 4) * 16;
    int aSw = (aRow & 7) * 16;
    int bRow = (lane & 7) + ((lane >> 4) & 1) * 8;
    int bColB = ((lane >> 3) & 1) * 16;
    int bSw = (bRow & 7) * 16;

#pragma unroll
    for (int ks = 0; ks < 2; ++ks) {
        uint32_t a0, a1, a2, a3;
        ldsm4(a0, a1, a2, a3, asb + aRow * 128 + ((ks * 32 + aColB) ^ aSw));
        int bcb = ks * 32 + bColB;
#pragma unroll
        for (int nb = 0; nb < 4; ++nb) {
            uint32_t c0, c1, c2, c3;
            int rowb = colGrp + nb * 16 + bRow;
            ldsm4(c0, c1, c2, c3, bsb + rowb * 128 + (bcb ^ bSw));
            mma16816(acc + nb * 8 + 0, a0, a1, a2, a3, c0, c1);
            mma16816(acc + nb * 8 + 4, a0, a1, a2, a3, c2, c3);
        }
    }

    int r0 = br + rg * 16 + (lane >> 2);
    int hA = colGrp >> 5;
    float elA0 = 0.f, elA1 = 0.f, elB0 = 0.f, elB1 = 0.f;
    float erA0 = 0.f, erA1 = 0.f, erB0 = 0.f, erB1 = 0.f;
#pragma unroll
    for (int nb = 0; nb < 4; ++nb) {
#pragma unroll
        for (int hf = 0; hf < 2; ++hf) {
            int ai = nb * 8 + hf * 4;
            int col0 = colGrp + nb * 16 + hf * 8 + (lane & 3) * 2;
            float w0 = als[col0];
            float w1 = als[col0 + 1];
            float u0 = ars[col0];
            float u1 = ars[col0 + 1];
            if (nb < 2) {
                elA0 += acc[ai] * w0 + acc[ai + 1] * w1;
                elA1 += acc[ai + 2] * w0 + acc[ai + 3] * w1;
                erA0 += acc[ai] * u0 + acc[ai + 1] * u1;
                erA1 += acc[ai + 2] * u0 + acc[ai + 3] * u1;
            } else {
                elB0 += acc[ai] * w0 + acc[ai + 1] * w1;
                elB1 += acc[ai + 2] * w0 + acc[ai + 3] * w1;
                erB0 += acc[ai] * u0 + acc[ai + 1] * u1;
                erB1 += acc[ai + 2] * u0 + acc[ai + 3] * u1;
            }
            if (r0 < NN)
                *reinterpret_cast<__half2*>(&Hout[(long)r0 * 128 + col0]) =
                    __floats2half2_rn(acc[ai], acc[ai + 1]);
            if (r0 + 8 < NN)
                *reinterpret_cast<__half2*>(&Hout[(long)(r0 + 8) * 128 + col0]) =
                    __floats2half2_rn(acc[ai + 2], acc[ai + 3]);
        }
    }
#pragma unroll
    for (int s = 1; s <= 2; s <<= 1) {
        elA0 += __shfl_xor_sync(0xffffffffu, elA0, s);
        elA1 += __shfl_xor_sync(0xffffffffu, elA1, s);
        elB0 += __shfl_xor_sync(0xffffffffu, elB0, s);
        elB1 += __shfl_xor_sync(0xffffffffu, elB1, s);
        erA0 += __shfl_xor_sync(0xffffffffu, erA0, s);
        erA1 += __shfl_xor_sync(0xffffffffu, erA1, s);
        erB0 += __shfl_xor_sync(0xffffffffu, erB0, s);
        erB1 += __shfl_xor_sync(0xffffffffu, erB1, s);
    }
    if ((lane & 3) == 0) {
        int hB = hA + 1;
        if (r0 < NN) {
            ELout[r0 * 4 + hA] = elA0;
            ELout[r0 * 4 + hB] = elB0;
            ERout[r0 * 4 + hA] = erA0;
            ERout[r0 * 4 + hB] = erB0;
        }
        if (r0 + 8 < NN) {
            ELout[(r0 + 8) * 4 + hA] = elA1;
            ELout[(r0 + 8) * 4 + hB] = elB1;
            ERout[(r0 + 8) * 4 + hA] = erA1;
            ERout[(r0 + 8) * 4 + hB] = erB1;
        }
    }
}

// ---------------- GAT aggregation: 2 warps/block for tail balance -----------
__global__ void k_agg(const float* __restrict__ gb0, const float* __restrict__ gb1,
                      const float* __restrict__ gb2) {
    int wid = threadIdx.x >> 5;
    int lane = threadIdx.x & 31;
    int node = blockIdx.x * 2 + wid;
    if (node >= NN) return;
    const __half* H0 = g_h[0];
    const __half* H1 = g_h[1];
    const __half* H2 = g_h[2];
    const float* E0 = g_el[0];
    const float* E1 = g_el[1];
    const float* E2 = g_el[2];
    int head = lane >> 3;
    float er0 = g_er[0][node * 4 + head];
    float er1 = g_er[1][node * 4 + head];
    float er2 = g_er[2][node * 4 + head];
    int beg = g_rowptr[node];
    int end = g_rowptr[node + 1];

    float d0 = 0.f, d1 = 0.f, d2 = 0.f;
    float4 A0 = make_float4(0, 0, 0, 0);
    float4 A1 = make_float4(0, 0, 0, 0);
    float4 A2 = make_float4(0, 0, 0, 0);

    int sA = (beg < end) ? g_csrc[beg] : 0;
    int soA = sA * 4 + head;
    long hoA = (long)sA * 128 + lane * 4;
    float fA0 = E0[soA];
    float fA1 = E1[soA];
    float fA2 = E2[soA];
    uint2 vA0 = *reinterpret_cast<const uint2*>(&H0[hoA]);
    uint2 vA1 = *reinterpret_cast<const uint2*>(&H1[hoA]);
    uint2 vA2 = *reinterpret_cast<const uint2*>(&H2[hoA]);

    for (int i = beg; i < end; ++i) {
        int sB = (i + 1 < end) ? g_csrc[i + 1] : sA;
        int soB = sB * 4 + head;
        long hoB = (long)sB * 128 + lane * 4;
        float fB0 = E0[soB];
        float fB1 = E1[soB];
        float fB2 = E2[soB];
        uint2 vB0 = *reinterpret_cast<const uint2*>(&H0[hoB]);
        uint2 vB1 = *reinterpret_cast<const uint2*>(&H1[hoB]);
        uint2 vB2 = *reinterpret_cast<const uint2*>(&H2[hoB]);

        float e0 = fA0 + er0;
        e0 = (e0 > 0.f) ? e0 : 0.2f * e0;
        float e1 = fA1 + er1;
        e1 = (e1 > 0.f) ? e1 : 0.2f * e1;
        float e2 = fA2 + er2;
        e2 = (e2 > 0.f) ? e2 : 0.2f * e2;
        float a0 = __expf(e0);
        float a1 = __expf(e1);
        float a2 = __expf(e2);
        float2 p, q;
        p = __half22float2(*reinterpret_cast<__half2*>(&vA0.x));
        q = __half22float2(*reinterpret_cast<__half2*>(&vA0.y));
        d0 += a0;
        A0.x += a0 * p.x; A0.y += a0 * p.y; A0.z += a0 * q.x; A0.w += a0 * q.y;
        p = __half22float2(*reinterpret_cast<__half2*>(&vA1.x));
        q = __half22float2(*reinterpret_cast<__half2*>(&vA1.y));
        d1 += a1;
        A1.x += a1 * p.x; A1.y += a1 * p.y; A1.z += a1 * q.x; A1.w += a1 * q.y;
        p = __half22float2(*reinterpret_cast<__half2*>(&vA2.x));
        q = __half22float2(*reinterpret_cast<__half2*>(&vA2.y));
        d2 += a2;
        A2.x += a2 * p.x; A2.y += a2 * p.y; A2.z += a2 * q.x; A2.w += a2 * q.y;

        fA0 = fB0; fA1 = fB1; fA2 = fB2;
        vA0 = vB0; vA1 = vB1; vA2 = vB2;
    }
    float i0 = 1.f / fmaxf(d0, 1e-9f);
    float i1 = 1.f / fmaxf(d1, 1e-9f);
    float i2 = 1.f / fmaxf(d2, 1e-9f);
    int c = lane * 4;
    uint2 st;
    __half2* sp = reinterpret_cast<__half2*>(&st);
    sp[0] = __floats2half2_rn(A0.x * i0 + gb0[c], A0.y * i0 + gb0[c + 1]);
    sp[1] = __floats2half2_rn(A0.z * i0 + gb0[c + 2], A0.w * i0 + gb0[c + 3]);
    *reinterpret_cast<uint2*>(&g_comb[(long)node * 384 + c]) = st;
    sp[0] = __floats2half2_rn(A1.x * i1 + gb1[c], A1.y * i1 + gb1[c + 1]);
    sp[1] = __floats2half2_rn(A1.z * i1 + gb1[c + 2], A1.w * i1 + gb1[c + 3]);
    *reinterpret_cast<uint2*>(&g_comb[(long)node * 384 + 128 + c]) = st;
    sp[0] = __floats2half2_rn(A2.x * i2 + gb2[c], A2.y * i2 + gb2[c + 1]);
    sp[1] = __floats2half2_rn(A2.z * i2 + gb2[c + 2], A2.w * i2 + gb2[c + 3]);
    *reinterpret_cast<uint2*>(&g_comb[(long)node * 384 + 256 + c]) = st;
}

// ---------------- final FC via HMMA (comb is fp16: A-stage is byte copy) ----
__global__ void __launch_bounds__(256) k_fc(const float* __restrict__ Wf,
                                            const float* __restrict__ bf,
                                            float* __restrict__ out) {
    __shared__ __half As[2][64 * 64];
    __shared__ __half Bs[2][128 * 64];
    int t = threadIdx.x;
    int lane = t & 31;
    int w = t >> 5;
    int br = blockIdx.x * 64;
    uint32_t asb = (uint32_t)__cvta_generic_to_shared(&As[0][0]);
    uint32_t bsb = (uint32_t)__cvta_generic_to_shared(&Bs[0][0]);

    float acc[32];
#pragma unroll
    for (int i = 0; i < 32; ++i) acc[i] = 0.f;

    int aRow = (w >> 1) * 16 + (lane & 15);
    int aColB = (lane >> 4) * 16;
    int aSw = (aRow & 7) * 16;
    int bRow = (lane & 7) + ((lane >> 4) & 1) * 8;
    int bColB = ((lane >> 3) & 1) * 16;
    int bSw = (bRow & 7) * 16;
    int colGrp = (w & 1) * 64;

    int sr = t >> 4;
    int sc4 = (t & 15) * 4;

    uint4 va[2];
    float4 vb[8];

#pragma unroll
    for (int i = 0; i < 2; ++i) {
        int idx = i * 256 + t;
        int r = idx >> 3;
        int ch = (idx & 7) * 8;
        int row = br + r;
        if (row >= NN) row = NN - 1;
        va[i] = *reinterpret_cast<const uint4*>(&g_comb[(long)row * 384 + ch]);
    }
#pragma unroll
    for (int i = 0; i < 8; ++i) {
        int r = i * 16 + sr;
        vb[i] = *reinterpret_cast<const float4*>(&Wf[r * 384 + sc4]);
    }
#pragma unroll
    for (int i = 0; i < 2; ++i) {
        int idx = i * 256 + t;
        int r = idx >> 3;
        int cb = (idx & 7) * 16;
        int off = r * 128 + (cb ^ ((r & 7) * 16));
        *reinterpret_cast<uint4*>(reinterpret_cast<char*>(&As[0][0]) + off) = va[i];
    }
#pragma unroll
    for (int i = 0; i < 8; ++i) {
        int r = i * 16 + sr;
        int off = r * 128 + ((sc4 * 2) ^ ((r & 7) * 16));
        __half2* p = reinterpret_cast<__half2*>(reinterpret_cast<char*>(&Bs[0][0]) + off);
        p[0] = __floats2half2_rn(vb[i].x, vb[i].y);
        p[1] = __floats2half2_rn(vb[i].z, vb[i].w);
    }
    __syncthreads();

    const int nIter = 6;
    for (int it = 0; it < nIter; ++it) {
        int cur = it & 1;
        if (it + 1 < nIter) {
            int k0 = (it + 1) * 64;
#pragma unroll
            for (int i = 0; i < 2; ++i) {
                int idx = i * 256 + t;
                int r = idx >> 3;
                int ch = (idx & 7) * 8;
                int row = br + r;
                if (row >= NN) row = NN - 1;
                va[i] = *reinterpret_cast<const uint4*>(
                    &g_comb[(long)row * 384 + k0 + ch]);
            }
#pragma unroll
            for (int i = 0; i < 8; ++i) {
                int r = i * 16 + sr;
                vb[i] = *reinterpret_cast<const float4*>(&Wf[r * 384 + k0 + sc4]);
            }
        }
        uint32_t aBase = asb + cur * 8192 + aRow * 128;
        uint32_t bBase = bsb + cur * 16384;
#pragma unroll
        for (int ks = 0; ks < 4; ++ks) {
            uint32_t a0, a1, a2, a3;
            ldsm4(a0, a1, a2, a3, aBase + ((ks * 32 + aColB) ^ aSw));
            int bcb = ks * 32 + bColB;
#pragma unroll
            for (int nb = 0; nb < 4; ++nb) {
                uint32_t c0, c1, c2, c3;
                int rowb = colGrp + nb * 16 + bRow;
                ldsm4(c0, c1, c2, c3, bBase + rowb * 128 + (bcb ^ bSw));
                mma16816(acc + nb * 8 + 0, a0, a1, a2, a3, c0, c1);
                mma16816(acc + nb * 8 + 4, a0, a1, a2, a3, c2, c3);
            }
        }
        if (it + 1 < nIter) {
            int nxt = 1 - cur;
#pragma unroll
            for (int i = 0; i < 2; ++i) {
                int idx = i * 256 + t;
                int r = idx >> 3;
                int cb = (idx & 7) * 16;
                int off = r * 128 + (cb ^ ((r & 7) * 16));
                *reinterpret_cast<uint4*>(reinterpret_cast<char*>(&As[nxt][0]) + off) =
                    va[i];
            }
#pragma unroll
            for (int i = 0; i < 8; ++i) {
                int r = i * 16 + sr;
                int off = r * 128 + ((sc4 * 2) ^ ((r & 7) * 16));
                __half2* p = reinterpret_cast<__half2*>(
                    reinterpret_cast<char*>(&Bs[nxt][0]) + off);
                p[0] = __floats2half2_rn(vb[i].x, vb[i].y);
                p[1] = __floats2half2_rn(vb[i].z, vb[i].w);
            }
        }
        __syncthreads();
    }

    int r0 = br + (w >> 1) * 16 + (lane >> 2);
    int col0 = (lane & 3) * 2;
#pragma unroll
    for (int g = 0; g < 8; ++g) {
        int col = colGrp + g * 8 + col0;
        float bv0 = bf[col];
        float bv1 = bf[col + 1];
        if (r0 < NN) {
            float2 o;
            o.x = fmaxf(acc[g * 4 + 0] + bv0, 0.f);
            o.y = fmaxf(acc[g * 4 + 1] + bv1, 0.f);
            *reinterpret_cast<float2*>(&out[(long)r0 * 128 + col]) = o;
        }
        if (r0 + 8 < NN) {
            float2 o;
            o.x = fmaxf(acc[g * 4 + 2] + bv0, 0.f);
            o.y = fmaxf(acc[g * 4 + 3] + bv1, 0.f);
            *reinterpret_cast<float2*>(&out[(long)(r0 + 8) * 128 + col]) = o;
        }
    }
}

// ---------------- launch: fork/join two independent chains ------------------
extern "C" void kernel_launch(void* const* d_in, const int* in_sizes, int n_in,
                              void* d_out, int out_size) {
    const int* user_ids = (const int*)d_in[0];
    const int* item_ids = (const int*)d_in[1];
    const int* src = (const int*)d_in[2];
    const int* dst = (const int*)d_in[3];
    const float* feat0 = (const float*)d_in[4];
    const float* feat1 = (const float*)d_in[5];
    const float* feat2 = (const float*)d_in[6];
    const float* user_table = (const float*)d_in[7];
    const float* item_table = (const float*)d_in[8];
    const float* W0 = (const float*)d_in[9];
    const float* b0 = (const float*)d_in[10];
    const float* W1 = (const float*)d_in[11];
    const float* b1 = (const float*)d_in[12];
    const float* W2 = (const float*)d_in[13];
    const float* b2 = (const float*)d_in[14];
    const float* gW0 = (const float*)d_in[15];
    const float* al0 = (const float*)d_in[16];
    const float* ar0 = (const float*)d_in[17];
    const float* gb0 = (const float*)d_in[18];
    const float* gW1 = (const float*)d_in[19];
    const float* al1 = (const float*)d_in[20];
    const float* ar1 = (const float*)d_in[21];
    const float* gb1 = (const float*)d_in[22];
    const float* gW2 = (const float*)d_in[23];
    const float* al2 = (const float*)d_in[24];
    const float* ar2 = (const float*)d_in[25];
    const float* gb2 = (const float*)d_in[26];
    const float* fcW = (const float*)d_in[27];
    const float* fcb = (const float*)d_in[28];

    float* out = (float*)d_out;

    cudaStream_t s2;
    cudaStreamCreateWithFlags(&s2, cudaStreamNonBlocking);
    cudaEvent_t eFork, eJoin;
    cudaEventCreateWithFlags(&eFork, cudaEventDisableTiming);
    cudaEventCreateWithFlags(&eJoin, cudaEventDisableTiming);

    cudaEventRecord(eFork, 0);
    cudaStreamWaitEvent(s2, eFork, 0);

    // chain A on side stream: CSR build (+ embedding gathers)
    k_front<<<4096 + (NE + 255) / 256, 256, 0, s2>>>(user_ids, item_ids,
                                                     user_table, item_table,
                                                     out, dst);
    k_scan1<<<49, 1024, 0, s2>>>();
    k_scan2<<<1, 32, 0, s2>>>();
    k_scan3<<<49, 1024, 0, s2>>>();
    k_scatter<<<(NE + 255) / 256, 256, 0, s2>>>(src, dst);
    cudaEventRecord(eJoin, s2);

    // chain B on legacy stream: feature GEMMs
    k_lin32<<<dim3(391, 3), 256>>>(feat0, feat1, feat2, W0, W1, W2, b0, b1, b2);
    k_gatfc<<<dim3((NN + 63) / 64, 3), 256>>>(gW0, gW1, gW2, al0, al1, al2,
                                              ar0, ar1, ar2);

    // join, then dependent tail
    cudaStreamWaitEvent(0, eJoin, 0);
    k_agg<<<(NN + 1) / 2, 64>>>(gb0, gb1, gb2);
    k_fc<<<(NN + 63) / 64, 256>>>(fcW, fcb, out + 2 * BB * 128);

    cudaEventDestroy(eFork);
    cudaEventDestroy(eJoin);
    cudaStreamDestroy(s2);
}

// round 16
// speedup vs baseline: 1.3744x; 1.3744x over previous
#include <cuda_runtime.h>
#include <cuda_bf16.h>
#include <cuda_fp16.h>
#include <cstdint>
#include <math_constants.h>

#define NN 50000
#define NE 1600000
#define BB 16384

// ---------------- device scratch ----------------
// g_deg must be zero at entry of every kernel_launch call; k_scan3 restores it.
__device__ __align__(16) float g_x[3][NN * 32];
__device__ __align__(16) __half g_h[3][NN * 128];
__device__ __align__(16) float g_el[3][NN * 4];
__device__ __align__(16) float g_er[3][NN * 4];
__device__ __align__(16) __half g_comb[NN * 384];   // fp16 (numerically free)
__device__ int g_deg[NN];
__device__ int g_rowptr[NN + 1];
__device__ int g_cursor[NN];
__device__ int g_csrc[NE];
__device__ int g_bsum[64];
__device__ int g_bsum2[64];

// ---------------- tensor-core helpers ----------------
__device__ __forceinline__ void ldsm4(uint32_t& r0, uint32_t& r1, uint32_t& r2,
                                      uint32_t& r3, uint32_t addr) {
    asm volatile("ldmatrix.sync.aligned.m8n8.x4.shared.b16 {%0,%1,%2,%3},[%4];"
                 : "=r"(r0), "=r"(r1), "=r"(r2), "=r"(r3)
                 : "r"(addr));
}
__device__ __forceinline__ void mma16816(float* c, uint32_t a0, uint32_t a1,
                                         uint32_t a2, uint32_t a3, uint32_t b0,
                                         uint32_t b1) {
    asm volatile(
        "mma.sync.aligned.m16n8k16.row.col.f32.f16.f16.f32 "
        "{%0,%1,%2,%3},{%4,%5,%6,%7},{%8,%9},{%0,%1,%2,%3};"
        : "+f"(c[0]), "+f"(c[1]), "+f"(c[2]), "+f"(c[3])
        : "r"(a0), "r"(a1), "r"(a2), "r"(a3), "r"(b0), "r"(b1));
}

// ---------------- K0: embedding gathers + degree histogram ------------------
__global__ void k_front(const int* __restrict__ uid, const int* __restrict__ iid,
                        const float* __restrict__ ut, const float* __restrict__ it,
                        float* __restrict__ out, const int* __restrict__ dst) {
    int bx = blockIdx.x;
    if (bx < 4096) {
        int t = bx * 256 + threadIdx.x;
        int c = t & 31;
        int r = (t >> 5) & (BB - 1);
        int which = t >> 19;
        const float4* src = which ? (const float4*)it : (const float4*)ut;
        int id = which ? iid[r] : uid[r];
        float4* dstp = (float4*)out + (which ? BB * 32 : 0);
        dstp[r * 32 + c] = src[id * 32 + c];
    } else {
        int e = (bx - 4096) * 256 + threadIdx.x;
        if (e < NE) atomicAdd(&g_deg[dst[e]], 1);
    }
}

// ---------------- scan stage 1 ----------------------------------------------
__global__ void k_scan1() {
    __shared__ int ws[32];
    int t = threadIdx.x;
    int lane = t & 31;
    int w = t >> 5;
    int i = blockIdx.x * 1024 + t;
    int v = (i < NN) ? g_deg[i] : 0;
    int x = v;
#pragma unroll
    for (int d = 1; d < 32; d <<= 1) {
        int y = __shfl_up_sync(0xffffffffu, x, d);
        if (lane >= d) x += y;
    }
    if (lane == 31) ws[w] = x;
    __syncthreads();
    if (w == 0) {
        int s = ws[lane];
#pragma unroll
        for (int d = 1; d < 32; d <<= 1) {
            int y = __shfl_up_sync(0xffffffffu, s, d);
            if (lane >= d) s += y;
        }
        ws[lane] = s;
    }
    __syncthreads();
    int incl = x + (w ? ws[w - 1] : 0);
    if (i < NN) g_rowptr[i + 1] = incl;
    if (t == 1023) g_bsum[blockIdx.x] = incl;
}

// ---------------- scan stage 2 ----------------------------------------------
__global__ void k_scan2() {
    if (threadIdx.x == 0) {
        int run = 0;
#pragma unroll 1
        for (int b = 0; b < 49; ++b) {
            g_bsum2[b] = run;
            run += g_bsum[b];
        }
    }
}

// ---------------- scan stage 3 ----------------------------------------------
__global__ void k_scan3() {
    int i = blockIdx.x * 1024 + threadIdx.x;
    if (i < NN) {
        int off = g_bsum2[blockIdx.x];
        int incl = g_rowptr[i + 1] + off;
        g_rowptr[i + 1] = incl;
        g_cursor[i] = incl - g_deg[i];
        g_deg[i] = 0;
    }
    if (i == 0) g_rowptr[0] = 0;
}

// ---------------- CSR scatter ------------------------------------------------
__global__ void k_scatter(const int* __restrict__ src, const int* __restrict__ dst) {
    int e = blockIdx.x * 256 + threadIdx.x;
    if (e < NE) {
        int d = dst[e];
        int pos = atomicAdd(&g_cursor[d], 1);
        g_csrc[pos] = src[e];
    }
}

// ---------------- fused modality linears via HMMA, 2-stage pipeline ---------
__global__ void __launch_bounds__(256) k_lin32(
    const float* __restrict__ f0, const float* __restrict__ f1,
    const float* __restrict__ f2, const float* __restrict__ W0,
    const float* __restrict__ W1, const float* __restrict__ W2,
    const float* __restrict__ b0, const float* __restrict__ b1,
    const float* __restrict__ b2) {
    __shared__ __half As[2][128 * 64];
    __shared__ __half Bs[2][32 * 64];
    int m = blockIdx.y;
    const float* A = (m == 0) ? f0 : ((m == 1) ? f1 : f2);
    const float* W = (m == 0) ? W0 : ((m == 1) ? W1 : W2);
    const float* bias = (m == 0) ? b0 : ((m == 1) ? b1 : b2);
    const int K = (m == 0) ? 1024 : ((m == 1) ? 768 : 128);
    float* X = g_x[m];

    int t = threadIdx.x;
    int lane = t & 31;
    int w = t >> 5;
    int br = blockIdx.x * 128;
    uint32_t asb = (uint32_t)__cvta_generic_to_shared(&As[0][0]);
    uint32_t bsb = (uint32_t)__cvta_generic_to_shared(&Bs[0][0]);

    float acc[16];
#pragma unroll
    for (int i = 0; i < 16; ++i) acc[i] = 0.f;

    int aRow = w * 16 + (lane & 15);
    int aColB = (lane >> 4) * 16;
    int aSw = (aRow & 7) * 16;
    int bRow = (lane & 7) + ((lane >> 4) & 1) * 8;
    int bColB = ((lane >> 3) & 1) * 16;
    int bSw = (bRow & 7) * 16;

    int sr = t >> 4;
    int sc4 = (t & 15) * 4;

    float4 va[8];
    float4 vb[2];

#pragma unroll
    for (int i = 0; i < 8; ++i) {
        int r = i * 16 + sr;
        int row = br + r;
        if (row >= NN) row = NN - 1;
        va[i] = *reinterpret_cast<const float4*>(&A[(long)row * K + sc4]);
    }
#pragma unroll
    for (int i = 0; i < 2; ++i) {
        int r = i * 16 + sr;
        vb[i] = *reinterpret_cast<const float4*>(&W[r * K + sc4]);
    }
#pragma unroll
    for (int i = 0; i < 8; ++i) {
        int r = i * 16 + sr;
        int off = r * 128 + ((sc4 * 2) ^ ((r & 7) * 16));
        __half2* p = reinterpret_cast<__half2*>(reinterpret_cast<char*>(&As[0][0]) + off);
        p[0] = __floats2half2_rn(va[i].x, va[i].y);
        p[1] = __floats2half2_rn(va[i].z, va[i].w);
    }
#pragma unroll
    for (int i = 0; i < 2; ++i) {
        int r = i * 16 + sr;
        int off = r * 128 + ((sc4 * 2) ^ ((r & 7) * 16));
        __half2* p = reinterpret_cast<__half2*>(reinterpret_cast<char*>(&Bs[0][0]) + off);
        p[0] = __floats2half2_rn(vb[i].x, vb[i].y);
        p[1] = __floats2half2_rn(vb[i].z, vb[i].w);
    }
    __syncthreads();

    int nIter = K >> 6;
    for (int it = 0; it < nIter; ++it) {
        int cur = it & 1;
        if (it + 1 < nIter) {
            int k0 = (it + 1) * 64;
#pragma unroll
            for (int i = 0; i < 8; ++i) {
                int r = i * 16 + sr;
                int row = br + r;
                if (row >= NN) row = NN - 1;
                va[i] = *reinterpret_cast<const float4*>(&A[(long)row * K + k0 + sc4]);
            }
#pragma unroll
            for (int i = 0; i < 2; ++i) {
                int r = i * 16 + sr;
                vb[i] = *reinterpret_cast<const float4*>(&W[r * K + k0 + sc4]);
            }
        }
        uint32_t aBase = asb + cur * 16384 + aRow * 128;
        uint32_t bBase0 = bsb + cur * 4096 + bRow * 128;
        uint32_t bBase1 = bBase0 + 16 * 128;
#pragma unroll
        for (int ks = 0; ks < 4; ++ks) {
            uint32_t a0, a1, a2, a3;
            ldsm4(a0, a1, a2, a3, aBase + ((ks * 32 + aColB) ^ aSw));
            uint32_t c0, c1, c2, c3;
            uint32_t d0, d1, d2, d3;
            int bcb = ks * 32 + bColB;
            ldsm4(c0, c1, c2, c3, bBase0 + (bcb ^ bSw));
            ldsm4(d0, d1, d2, d3, bBase1 + (bcb ^ bSw));
            mma16816(acc + 0, a0, a1, a2, a3, c0, c1);
            mma16816(acc + 4, a0, a1, a2, a3, c2, c3);
            mma16816(acc + 8, a0, a1, a2, a3, d0, d1);
            mma16816(acc + 12, a0, a1, a2, a3, d2, d3);
        }
        if (it + 1 < nIter) {
            int nxt = 1 - cur;
#pragma unroll
            for (int i = 0; i < 8; ++i) {
                int r = i * 16 + sr;
                int off = r * 128 + ((sc4 * 2) ^ ((r & 7) * 16));
                __half2* p = reinterpret_cast<__half2*>(
                    reinterpret_cast<char*>(&As[nxt][0]) + off);
                p[0] = __floats2half2_rn(va[i].x, va[i].y);
                p[1] = __floats2half2_rn(va[i].z, va[i].w);
            }
#pragma unroll
            for (int i = 0; i < 2; ++i) {
                int r = i * 16 + sr;
                int off = r * 128 + ((sc4 * 2) ^ ((r & 7) * 16));
                __half2* p = reinterpret_cast<__half2*>(
                    reinterpret_cast<char*>(&Bs[nxt][0]) + off);
                p[0] = __floats2half2_rn(vb[i].x, vb[i].y);
                p[1] = __floats2half2_rn(vb[i].z, vb[i].w);
            }
        }
        __syncthreads();
    }

    int r0 = br + w * 16 + (lane >> 2);
    int col0 = (lane & 3) * 2;
#pragma unroll
    for (int g = 0; g < 4; ++g) {
        int col = g * 8 + col0;
        float bv0 = bias[col];
        float bv1 = bias[col + 1];
        if (r0 < NN) {
            float2 o;
            o.x = fmaxf(acc[g * 4 + 0] + bv0, 0.f);
            o.y = fmaxf(acc[g * 4 + 1] + bv1, 0.f);
            *reinterpret_cast<float2*>(&X[r0 * 32 + col]) = o;
        }
        if (r0 + 8 < NN) {
            float2 o;
            o.x = fmaxf(acc[g * 4 + 2] + bv0, 0.f);
            o.y = fmaxf(acc[g * 4 + 3] + bv1, 0.f);
            *reinterpret_cast<float2*>(&X[(r0 + 8) * 32 + col]) = o;
        }
    }
}

// ---------------- GAT fc via HMMA + fused attention logits ------------------
__global__ void __launch_bounds__(256) k_gatfc(
    const float* __restrict__ gW0, const float* __restrict__ gW1,
    const float* __restrict__ gW2, const float* __restrict__ al0,
    const float* __restrict__ al1, const float* __restrict__ al2,
    const float* __restrict__ ar0, const float* __restrict__ ar1,
    const float* __restrict__ ar2) {
    __shared__ __half As[64 * 64];
    __shared__ __half Bs[128 * 64];
    __shared__ float als[128];
    __shared__ float ars[128];
    int m = blockIdx.y;
    const float* gW = (m == 0) ? gW0 : ((m == 1) ? gW1 : gW2);
    const float* al = (m == 0) ? al0 : ((m == 1) ? al1 : al2);
    const float* ar = (m == 0) ? ar0 : ((m == 1) ? ar1 : ar2);
    const float* X = g_x[m];
    __half* Hout = g_h[m];
    float* ELout = g_el[m];
    float* ERout = g_er[m];

    int t = threadIdx.x;
    int lane = t & 31;
    int w = t >> 5;
    int br = blockIdx.x * 64;
    uint32_t asb = (uint32_t)__cvta_generic_to_shared(&As[0]);
    uint32_t bsb = (uint32_t)__cvta_generic_to_shared(&Bs[0]);

    if (t < 128) als[t] = al[t];
    else ars[t - 128] = ar[t - 128];

#pragma unroll
    for (int i = 0; i < 2; ++i) {
        int idx = i * 256 + t;
        int r = idx >> 3;
        int c4 = (idx & 7) * 4;
        int row = br + r;
        if (row >= NN) row = NN - 1;
        float4 v = *reinterpret_cast<const float4*>(&X[(long)row * 32 + c4]);
        int off = r * 128 + ((c4 * 2) ^ ((r & 7) * 16));
        __half2* p = reinterpret_cast<__half2*>(reinterpret_cast<char*>(&As[0]) + off);
        p[0] = __floats2half2_rn(v.x, v.y);
        p[1] = __floats2half2_rn(v.z, v.w);
    }
#pragma unroll
    for (int i = 0; i < 4; ++i) {
        int idx = i * 256 + t;
        int r = idx >> 3;
        int c4 = (idx & 7) * 4;
        float4 v = *reinterpret_cast<const float4*>(&gW[r * 32 + c4]);
        int off = r * 128 + ((c4 * 2) ^ ((r & 7) * 16));
        __half2* p = reinterpret_cast<__half2*>(reinterpret_cast<char*>(&Bs[0]) + off);
        p[0] = __floats2half2_rn(v.x, v.y);
        p[1] = __floats2half2_rn(v.z, v.w);
    }
    __syncthreads();

    float acc[32];
#pragma unroll
    for (int i = 0; i < 32; ++i) acc[i] = 0.f;

    int rg = w >> 1;
    int colGrp = (w & 1) * 64;
    int aRow = rg * 16 + (lane & 15);
    int aColB = (lane >> 4) * 16;
    int aSw = (aRow & 7) * 16;
    int bRow = (lane & 7) + ((lane >> 4) & 1) * 8;
    int bColB = ((lane >> 3) & 1) * 16;
    int bSw = (bRow & 7) * 16;

#pragma unroll
    for (int ks = 0; ks < 2; ++ks) {
        uint32_t a0, a1, a2, a3;
        ldsm4(a0, a1, a2, a3, asb + aRow * 128 + ((ks * 32 + aColB) ^ aSw));
        int bcb = ks * 32 + bColB;
#pragma unroll
        for (int nb = 0; nb < 4; ++nb) {
            uint32_t c0, c1, c2, c3;
            int rowb = colGrp + nb * 16 + bRow;
            ldsm4(c0, c1, c2, c3, bsb + rowb * 128 + (bcb ^ bSw));
            mma16816(acc + nb * 8 + 0, a0, a1, a2, a3, c0, c1);
            mma16816(acc + nb * 8 + 4, a0, a1, a2, a3, c2, c3);
        }
    }

    int r0 = br + rg * 16 + (lane >> 2);
    int hA = colGrp >> 5;
    float elA0 = 0.f, elA1 = 0.f, elB0 = 0.f, elB1 = 0.f;
    float erA0 = 0.f, erA1 = 0.f, erB0 = 0.f, erB1 = 0.f;
#pragma unroll
    for (int nb = 0; nb < 4; ++nb) {
#pragma unroll
        for (int hf = 0; hf < 2; ++hf) {
            int ai = nb * 8 + hf * 4;
            int col0 = colGrp + nb * 16 + hf * 8 + (lane & 3) * 2;
            float w0 = als[col0];
            float w1 = als[col0 + 1];
            float u0 = ars[col0];
            float u1 = ars[col0 + 1];
            if (nb < 2) {
                elA0 += acc[ai] * w0 + acc[ai + 1] * w1;
                elA1 += acc[ai + 2] * w0 + acc[ai + 3] * w1;
                erA0 += acc[ai] * u0 + acc[ai + 1] * u1;
                erA1 += acc[ai + 2] * u0 + acc[ai + 3] * u1;
            } else {
                elB0 += acc[ai] * w0 + acc[ai + 1] * w1;
                elB1 += acc[ai + 2] * w0 + acc[ai + 3] * w1;
                erB0 += acc[ai] * u0 + acc[ai + 1] * u1;
                erB1 += acc[ai + 2] * u0 + acc[ai + 3] * u1;
            }
            if (r0 < NN)
                *reinterpret_cast<__half2*>(&Hout[(long)r0 * 128 + col0]) =
                    __floats2half2_rn(acc[ai], acc[ai + 1]);
            if (r0 + 8 < NN)
                *reinterpret_cast<__half2*>(&Hout[(long)(r0 + 8) * 128 + col0]) =
                    __floats2half2_rn(acc[ai + 2], acc[ai + 3]);
        }
    }
#pragma unroll
    for (int s = 1; s <= 2; s <<= 1) {
        elA0 += __shfl_xor_sync(0xffffffffu, elA0, s);
        elA1 += __shfl_xor_sync(0xffffffffu, elA1, s);
        elB0 += __shfl_xor_sync(0xffffffffu, elB0, s);
        elB1 += __shfl_xor_sync(0xffffffffu, elB1, s);
        erA0 += __shfl_xor_sync(0xffffffffu, erA0, s);
        erA1 += __shfl_xor_sync(0xffffffffu, erA1, s);
        erB0 += __shfl_xor_sync(0xffffffffu, erB0, s);
        erB1 += __shfl_xor_sync(0xffffffffu, erB1, s);
    }
    if ((lane & 3) == 0) {
        int hB = hA + 1;
        if (r0 < NN) {
            ELout[r0 * 4 + hA] = elA0;
            ELout[r0 * 4 + hB] = elB0;
            ERout[r0 * 4 + hA] = erA0;
            ERout[r0 * 4 + hB] = erB0;
        }
        if (r0 + 8 < NN) {
            ELout[(r0 + 8) * 4 + hA] = elA1;
            ELout[(r0 + 8) * 4 + hB] = elB1;
            ERout[(r0 + 8) * 4 + hA] = erA1;
            ERout[(r0 + 8) * 4 + hB] = erB1;
        }
    }
}

// ---------------- GAT aggregation: 8 nodes/block (256 thr), pipelined -------
__global__ void k_agg(const float* __restrict__ gb0, const float* __restrict__ gb1,
                      const float* __restrict__ gb2) {
    int wid = threadIdx.x >> 5;
    int lane = threadIdx.x & 31;
    int node = blockIdx.x * 8 + wid;
    if (node >= NN) return;
    const __half* H0 = g_h[0];
    const __half* H1 = g_h[1];
    const __half* H2 = g_h[2];
    const float* E0 = g_el[0];
    const float* E1 = g_el[1];
    const float* E2 = g_el[2];
    int head = lane >> 3;
    float er0 = g_er[0][node * 4 + head];
    float er1 = g_er[1][node * 4 + head];
    float er2 = g_er[2][node * 4 + head];
    int beg = g_rowptr[node];
    int end = g_rowptr[node + 1];

    float d0 = 0.f, d1 = 0.f, d2 = 0.f;
    float4 A0 = make_float4(0, 0, 0, 0);
    float4 A1 = make_float4(0, 0, 0, 0);
    float4 A2 = make_float4(0, 0, 0, 0);

    int sA = (beg < end) ? g_csrc[beg] : 0;
    int soA = sA * 4 + head;
    long hoA = (long)sA * 128 + lane * 4;
    float fA0 = E0[soA];
    float fA1 = E1[soA];
    float fA2 = E2[soA];
    uint2 vA0 = *reinterpret_cast<const uint2*>(&H0[hoA]);
    uint2 vA1 = *reinterpret_cast<const uint2*>(&H1[hoA]);
    uint2 vA2 = *reinterpret_cast<const uint2*>(&H2[hoA]);

    for (int i = beg; i < end; ++i) {
        int sB = (i + 1 < end) ? g_csrc[i + 1] : sA;
        int soB = sB * 4 + head;
        long hoB = (long)sB * 128 + lane * 4;
        float fB0 = E0[soB];
        float fB1 = E1[soB];
        float fB2 = E2[soB];
        uint2 vB0 = *reinterpret_cast<const uint2*>(&H0[hoB]);
        uint2 vB1 = *reinterpret_cast<const uint2*>(&H1[hoB]);
        uint2 vB2 = *reinterpret_cast<const uint2*>(&H2[hoB]);

        float e0 = fA0 + er0;
        e0 = (e0 > 0.f) ? e0 : 0.2f * e0;
        float e1 = fA1 + er1;
        e1 = (e1 > 0.f) ? e1 : 0.2f * e1;
        float e2 = fA2 + er2;
        e2 = (e2 > 0.f) ? e2 : 0.2f * e2;
        float a0 = __expf(e0);
        float a1 = __expf(e1);
        float a2 = __expf(e2);
        float2 p, q;
        p = __half22float2(*reinterpret_cast<__half2*>(&vA0.x));
        q = __half22float2(*reinterpret_cast<__half2*>(&vA0.y));
        d0 += a0;
        A0.x += a0 * p.x; A0.y += a0 * p.y; A0.z += a0 * q.x; A0.w += a0 * q.y;
        p = __half22float2(*reinterpret_cast<__half2*>(&vA1.x));
        q = __half22float2(*reinterpret_cast<__half2*>(&vA1.y));
        d1 += a1;
        A1.x += a1 * p.x; A1.y += a1 * p.y; A1.z += a1 * q.x; A1.w += a1 * q.y;
        p = __half22float2(*reinterpret_cast<__half2*>(&vA2.x));
        q = __half22float2(*reinterpret_cast<__half2*>(&vA2.y));
        d2 += a2;
        A2.x += a2 * p.x; A2.y += a2 * p.y; A2.z += a2 * q.x; A2.w += a2 * q.y;

        fA0 = fB0; fA1 = fB1; fA2 = fB2;
        vA0 = vB0; vA1 = vB1; vA2 = vB2;
    }
    float i0 = 1.f / fmaxf(d0, 1e-9f);
    float i1 = 1.f / fmaxf(d1, 1e-9f);
    float i2 = 1.f / fmaxf(d2, 1e-9f);
    int c = lane * 4;
    uint2 st;
    __half2* sp = reinterpret_cast<__half2*>(&st);
    sp[0] = __floats2half2_rn(A0.x * i0 + gb0[c], A0.y * i0 + gb0[c + 1]);
    sp[1] = __floats2half2_rn(A0.z * i0 + gb0[c + 2], A0.w * i0 + gb0[c + 3]);
    *reinterpret_cast<uint2*>(&g_comb[(long)node * 384 + c]) = st;
    sp[0] = __floats2half2_rn(A1.x * i1 + gb1[c], A1.y * i1 + gb1[c + 1]);
    sp[1] = __floats2half2_rn(A1.z * i1 + gb1[c + 2], A1.w * i1 + gb1[c + 3]);
    *reinterpret_cast<uint2*>(&g_comb[(long)node * 384 + 128 + c]) = st;
    sp[0] = __floats2half2_rn(A2.x * i2 + gb2[c], A2.y * i2 + gb2[c + 1]);
    sp[1] = __floats2half2_rn(A2.z * i2 + gb2[c + 2], A2.w * i2 + gb2[c + 3]);
    *reinterpret_cast<uint2*>(&g_comb[(long)node * 384 + 256 + c]) = st;
}

// ---------------- final FC via HMMA (comb is fp16: A-stage is byte copy) ----
__global__ void __launch_bounds__(256) k_fc(const float* __restrict__ Wf,
                                            const float* __restrict__ bf,
                                            float* __restrict__ out) {
    __shared__ __half As[2][64 * 64];
    __shared__ __half Bs[2][128 * 64];
    int t = threadIdx.x;
    int lane = t & 31;
    int w = t >> 5;
    int br = blockIdx.x * 64;
    uint32_t asb = (uint32_t)__cvta_generic_to_shared(&As[0][0]);
    uint32_t bsb = (uint32_t)__cvta_generic_to_shared(&Bs[0][0]);

    float acc[32];
#pragma unroll
    for (int i = 0; i < 32; ++i) acc[i] = 0.f;

    int aRow = (w >> 1) * 16 + (lane & 15);
    int aColB = (lane >> 4) * 16;
    int aSw = (aRow & 7) * 16;
    int bRow = (lane & 7) + ((lane >> 4) & 1) * 8;
    int bColB = ((lane >> 3) & 1) * 16;
    int bSw = (bRow & 7) * 16;
    int colGrp = (w & 1) * 64;

    int sr = t >> 4;
    int sc4 = (t & 15) * 4;

    uint4 va[2];
    float4 vb[8];

#pragma unroll
    for (int i = 0; i < 2; ++i) {
        int idx = i * 256 + t;
        int r = idx >> 3;
        int ch = (idx & 7) * 8;
        int row = br + r;
        if (row >= NN) row = NN - 1;
        va[i] = *reinterpret_cast<const uint4*>(&g_comb[(long)row * 384 + ch]);
    }
#pragma unroll
    for (int i = 0; i < 8; ++i) {
        int r = i * 16 + sr;
        vb[i] = *reinterpret_cast<const float4*>(&Wf[r * 384 + sc4]);
    }
#pragma unroll
    for (int i = 0; i < 2; ++i) {
        int idx = i * 256 + t;
        int r = idx >> 3;
        int cb = (idx & 7) * 16;
        int off = r * 128 + (cb ^ ((r & 7) * 16));
        *reinterpret_cast<uint4*>(reinterpret_cast<char*>(&As[0][0]) + off) = va[i];
    }
#pragma unroll
    for (int i = 0; i < 8; ++i) {
        int r = i * 16 + sr;
        int off = r * 128 + ((sc4 * 2) ^ ((r & 7) * 16));
        __half2* p = reinterpret_cast<__half2*>(reinterpret_cast<char*>(&Bs[0][0]) + off);
        p[0] = __floats2half2_rn(vb[i].x, vb[i].y);
        p[1] = __floats2half2_rn(vb[i].z, vb[i].w);
    }
    __syncthreads();

    const int nIter = 6;
    for (int it = 0; it < nIter; ++it) {
        int cur = it & 1;
        if (it + 1 < nIter) {
            int k0 = (it + 1) * 64;
#pragma unroll
            for (int i = 0; i < 2; ++i) {
                int idx = i * 256 + t;
                int r = idx >> 3;
                int ch = (idx & 7) * 8;
                int row = br + r;
                if (row >= NN) row = NN - 1;
                va[i] = *reinterpret_cast<const uint4*>(
                    &g_comb[(long)row * 384 + k0 + ch]);
            }
#pragma unroll
            for (int i = 0; i < 8; ++i) {
                int r = i * 16 + sr;
                vb[i] = *reinterpret_cast<const float4*>(&Wf[r * 384 + k0 + sc4]);
            }
        }
        uint32_t aBase = asb + cur * 8192 + aRow * 128;
        uint32_t bBase = bsb + cur * 16384;
#pragma unroll
        for (int ks = 0; ks < 4; ++ks) {
            uint32_t a0, a1, a2, a3;
            ldsm4(a0, a1, a2, a3, aBase + ((ks * 32 + aColB) ^ aSw));
            int bcb = ks * 32 + bColB;
#pragma unroll
            for (int nb = 0; nb < 4; ++nb) {
                uint32_t c0, c1, c2, c3;
                int rowb = colGrp + nb * 16 + bRow;
                ldsm4(c0, c1, c2, c3, bBase + rowb * 128 + (bcb ^ bSw));
                mma16816(acc + nb * 8 + 0, a0, a1, a2, a3, c0, c1);
                mma16816(acc + nb * 8 + 4, a0, a1, a2, a3, c2, c3);
            }
        }
        if (it + 1 < nIter) {
            int nxt = 1 - cur;
#pragma unroll
            for (int i = 0; i < 2; ++i) {
                int idx = i * 256 + t;
                int r = idx >> 3;
                int cb = (idx & 7) * 16;
                int off = r * 128 + (cb ^ ((r & 7) * 16));
                *reinterpret_cast<uint4*>(reinterpret_cast<char*>(&As[nxt][0]) + off) =
                    va[i];
            }
#pragma unroll
            for (int i = 0; i < 8; ++i) {
                int r = i * 16 + sr;
                int off = r * 128 + ((sc4 * 2) ^ ((r & 7) * 16));
                __half2* p = reinterpret_cast<__half2*>(
                    reinterpret_cast<char*>(&Bs[nxt][0]) + off);
                p[0] = __floats2half2_rn(vb[i].x, vb[i].y);
                p[1] = __floats2half2_rn(vb[i].z, vb[i].w);
            }
        }
        __syncthreads();
    }

    int r0 = br + (w >> 1) * 16 + (lane >> 2);
    int col0 = (lane & 3) * 2;
#pragma unroll
    for (int g = 0; g < 8; ++g) {
        int col = colGrp + g * 8 + col0;
        float bv0 = bf[col];
        float bv1 = bf[col + 1];
        if (r0 < NN) {
            float2 o;
            o.x = fmaxf(acc[g * 4 + 0] + bv0, 0.f);
            o.y = fmaxf(acc[g * 4 + 1] + bv1, 0.f);
            *reinterpret_cast<float2*>(&out[(long)r0 * 128 + col]) = o;
        }
        if (r0 + 8 < NN) {
            float2 o;
            o.x = fmaxf(acc[g * 4 + 2] + bv0, 0.f);
            o.y = fmaxf(acc[g * 4 + 3] + bv1, 0.f);
            *reinterpret_cast<float2*>(&out[(long)(r0 + 8) * 128 + col]) = o;
        }
    }
}

// ---------------- launch: fork/join two independent chains ------------------
extern "C" void kernel_launch(void* const* d_in, const int* in_sizes, int n_in,
                              void* d_out, int out_size) {
    const int* user_ids = (const int*)d_in[0];
    const int* item_ids = (const int*)d_in[1];
    const int* src = (const int*)d_in[2];
    const int* dst = (const int*)d_in[3];
    const float* feat0 = (const float*)d_in[4];
    const float* feat1 = (const float*)d_in[5];
    const float* feat2 = (const float*)d_in[6];
    const float* user_table = (const float*)d_in[7];
    const float* item_table = (const float*)d_in[8];
    const float* W0 = (const float*)d_in[9];
    const float* b0 = (const float*)d_in[10];
    const float* W1 = (const float*)d_in[11];
    const float* b1 = (const float*)d_in[12];
    const float* W2 = (const float*)d_in[13];
    const float* b2 = (const float*)d_in[14];
    const float* gW0 = (const float*)d_in[15];
    const float* al0 = (const float*)d_in[16];
    const float* ar0 = (const float*)d_in[17];
    const float* gb0 = (const float*)d_in[18];
    const float* gW1 = (const float*)d_in[19];
    const float* al1 = (const float*)d_in[20];
    const float* ar1 = (const float*)d_in[21];
    const float* gb1 = (const float*)d_in[22];
    const float* gW2 = (const float*)d_in[23];
    const float* al2 = (const float*)d_in[24];
    const float* ar2 = (const float*)d_in[25];
    const float* gb2 = (const float*)d_in[26];
    const float* fcW = (const float*)d_in[27];
    const float* fcb = (const float*)d_in[28];

    float* out = (float*)d_out;

    cudaStream_t s2;
    cudaStreamCreateWithFlags(&s2, cudaStreamNonBlocking);
    cudaEvent_t eFork, eJoin;
    cudaEventCreateWithFlags(&eFork, cudaEventDisableTiming);
    cudaEventCreateWithFlags(&eJoin, cudaEventDisableTiming);

    cudaEventRecord(eFork, 0);
    cudaStreamWaitEvent(s2, eFork, 0);

    // chain A on side stream: CSR build (+ embedding gathers)
    k_front<<<4096 + (NE + 255) / 256, 256, 0, s2>>>(user_ids, item_ids,
                                                     user_table, item_table,
                                                     out, dst);
    k_scan1<<<49, 1024, 0, s2>>>();
    k_scan2<<<1, 32, 0, s2>>>();
    k_scan3<<<49, 1024, 0, s2>>>();
    k_scatter<<<(NE + 255) / 256, 256, 0, s2>>>(src, dst);
    cudaEventRecord(eJoin, s2);

    // chain B on legacy stream: feature GEMMs
    k_lin32<<<dim3(391, 3), 256>>>(feat0, feat1, feat2, W0, W1, W2, b0, b1, b2);
    k_gatfc<<<dim3((NN + 63) / 64, 3), 256>>>(gW0, gW1, gW2, al0, al1, al2,
                                              ar0, ar1, ar2);

    // join, then dependent tail
    cudaStreamWaitEvent(0, eJoin, 0);
    k_agg<<<(NN + 7) / 8, 256>>>(gb0, gb1, gb2);
    k_fc<<<(NN + 63) / 64, 256>>>(fcW, fcb, out + 2 * BB * 128);

    cudaEventDestroy(eFork);
    cudaEventDestroy(eJoin);
    cudaStreamDestroy(s2);
}